// round 16
// baseline (speedup 1.0000x reference)
#include <cuda_runtime.h>
#include <cuda_fp16.h>
#include <cuda_bf16.h>

#define N_NODES 100000
#define D_DIM   64
#define E_EDGES 1600000

#define SCAN_BLOCK 1024
#define N_SCAN_BLOCKS ((N_NODES + SCAN_BLOCK - 1) / SCAN_BLOCK)   // 98

// ---- device scratch (no cudaMalloc allowed; zero-initialized at load) ----
__device__ float  g_adst[N_NODES];          // h[i].w_dst + bias
__device__ float2 g_spack[N_NODES];         // (h[i].w_src, dnorm[i])
__device__ int    g_counts[N_NODES];        // in-degree histogram
                                            // INVARIANT: zero on kernel_launch entry
                                            // (re-zeroed by add_base_kernel each call)
__device__ int    g_offsets[N_NODES + 1];   // CSR row offsets
__device__ int    g_rank[E_EDGES];          // edge rank within its dst bucket
__device__ int    g_blocksums[N_SCAN_BLOCKS];
__device__ int    g_edge_src[E_EDGES];      // CSR column (src node) list

__device__ __forceinline__ float fast_tanh(float x) {
    float r;
    asm("tanh.approx.f32 %0, %1;" : "=f"(r) : "f"(x));
    return r;
}

__device__ __forceinline__ int warp_incl_scan(int v, int lane) {
    #pragma unroll
    for (int off = 1; off < 32; off <<= 1) {
        int t = __shfl_up_sync(0xFFFFFFFFu, v, off);
        if (lane >= off) v += t;
    }
    return v;
}

// ---------------------------------------------------------------------------
// K1: histogram + rank. 4 edges/thread, int4 I/O.
// ---------------------------------------------------------------------------
__global__ void hist_kernel(const int* __restrict__ dst)
{
    int t = blockIdx.x * blockDim.x + threadIdx.x;
    if (t >= E_EDGES / 4) return;

    int4 d4 = reinterpret_cast<const int4*>(dst)[t];
    int4 r4;
    r4.x = atomicAdd(&g_counts[d4.x], 1);
    r4.y = atomicAdd(&g_counts[d4.y], 1);
    r4.z = atomicAdd(&g_counts[d4.z], 1);
    r4.w = atomicAdd(&g_counts[d4.w], 1);
    reinterpret_cast<int4*>(g_rank)[t] = r4;
}

// ---------------------------------------------------------------------------
// K2: per-block exclusive scan via warp shuffles (2 syncs), writes block sums
// ---------------------------------------------------------------------------
__global__ void scan_blocks_kernel()
{
    __shared__ int warpsum[32];
    int tid  = threadIdx.x;
    int lane = tid & 31;
    int w    = tid >> 5;
    int i    = blockIdx.x * SCAN_BLOCK + tid;

    int v = (i < N_NODES) ? g_counts[i] : 0;
    int incl = warp_incl_scan(v, lane);
    if (lane == 31) warpsum[w] = incl;
    __syncthreads();

    if (w == 0) {
        int s = warpsum[lane];
        warpsum[lane] = warp_incl_scan(s, lane) - s;   // exclusive warp bases
    }
    __syncthreads();

    int total = incl - v + warpsum[w];                 // exclusive within block
    if (i < N_NODES) g_offsets[i] = total;
    if (tid == SCAN_BLOCK - 1) g_blocksums[blockIdx.x] = total + v;
}

// ---------------------------------------------------------------------------
// K3: add block bases (warp-0 shuffle scan over 98 sums), re-zero counts,
// fix offsets[N].
// ---------------------------------------------------------------------------
__global__ void add_base_kernel()
{
    __shared__ int sbase[1];
    int tid  = threadIdx.x;
    int lane = tid & 31;

    if (tid < 32) {
        int base = 0;
        int my = 0;
        #pragma unroll
        for (int c = 0; c < (N_SCAN_BLOCKS + 31) / 32; c++) {
            int idx = c * 32 + lane;
            int v = (idx < N_SCAN_BLOCKS) ? g_blocksums[idx] : 0;
            int incl = warp_incl_scan(v, lane);
            int excl = base + incl - v;
            if (idx == (int)blockIdx.x) my = excl;
            base += __shfl_sync(0xFFFFFFFFu, incl, 31);
        }
        #pragma unroll
        for (int off = 16; off > 0; off >>= 1)
            my += __shfl_xor_sync(0xFFFFFFFFu, my, off);
        if (lane == 0) sbase[0] = my;
    }
    __syncthreads();
    int base = sbase[0];

    int i = blockIdx.x * SCAN_BLOCK + tid;
    if (i < N_NODES) {
        g_offsets[i] = g_offsets[i] + base;
        g_counts[i]  = 0;          // restore K1's invariant for next replay
    }
    if (blockIdx.x == 0 && tid == 0) g_offsets[N_NODES] = E_EDGES;
}

// ---------------------------------------------------------------------------
// K4: FUSED atomic-free CSR scatter + node dots (no fp16 mirror anymore —
// gather reads h in fp32 directly; saves the 12.8MB mirror write).
// ---------------------------------------------------------------------------
__global__ void scatter_nodes_kernel(const int*   __restrict__ src,
                                     const int*   __restrict__ dst,
                                     const float* __restrict__ h,
                                     const float* __restrict__ dnorm,
                                     const float* __restrict__ gate_w,
                                     const float* __restrict__ gate_b)
{
    int t = blockIdx.x * blockDim.x + threadIdx.x;

    // ---- scatter part: 4 edges per thread ----
    if (t < E_EDGES / 4) {
        int4 s4 = reinterpret_cast<const int4*>(src)[t];
        int4 d4 = reinterpret_cast<const int4*>(dst)[t];
        int4 r4 = reinterpret_cast<const int4*>(g_rank)[t];

        int o0 = g_offsets[d4.x];
        int o1 = g_offsets[d4.y];
        int o2 = g_offsets[d4.z];
        int o3 = g_offsets[d4.w];

        g_edge_src[o0 + r4.x] = s4.x;
        g_edge_src[o1 + r4.y] = s4.y;
        g_edge_src[o2 + r4.z] = s4.z;
        g_edge_src[o3 + r4.w] = s4.w;
    }

    // ---- node part: warp handles 8 consecutive nodes ----
    int w    = t >> 5;
    int lane = t & 31;
    int nbase = w * 8;
    if (nbase >= N_NODES) return;

    float2 wd = *reinterpret_cast<const float2*>(gate_w + lane * 2);
    float2 ws = *reinterpret_cast<const float2*>(gate_w + D_DIM + lane * 2);
    float bias = gate_b[0];

    #pragma unroll
    for (int k = 0; k < 8; k++) {
        int node = nbase + k;
        if (node >= N_NODES) break;

        float2 hv = *reinterpret_cast<const float2*>(h + (long long)node * D_DIM + lane * 2);

        float pd = hv.x * wd.x + hv.y * wd.y;
        float ps = hv.x * ws.x + hv.y * ws.y;

        #pragma unroll
        for (int off = 16; off > 0; off >>= 1) {
            pd += __shfl_xor_sync(0xFFFFFFFFu, pd, off);
            ps += __shfl_xor_sync(0xFFFFFFFFu, ps, off);
        }

        if (lane == 0) {
            g_adst[node]  = pd + bias;
            g_spack[node] = make_float2(ps, dnorm[node]);
        }
    }
}

// ---------------------------------------------------------------------------
// K5: gather-accumulate. Warp per node; (s, coef) staged in smem per 32-edge
// chunk; h read DIRECTLY in fp32 (float2/lane) — no converts in the inner
// loop (gather is issue-bound, L2 has headroom). Addresses via
// (long long)s * D_DIM (IMAD.WIDE; do NOT pre-multiply). Unroll x8.
// ---------------------------------------------------------------------------
__global__ void gather_kernel(const float* __restrict__ h,
                              const float* __restrict__ dnorm,
                              float* __restrict__ out)
{
    __shared__ int2 stage[8][32];     // 8 warps per 256-thread block

    int tid  = blockIdx.x * blockDim.x + threadIdx.x;
    int d    = tid >> 5;
    int w    = (threadIdx.x >> 5);
    int lane = tid & 31;
    if (d >= N_NODES) return;

    int beg = g_offsets[d];
    int end = g_offsets[d + 1];

    float adst_d = g_adst[d];
    float dnd    = dnorm[d];

    float accx = 0.f, accy = 0.f;

    for (int base = beg; base < end; base += 32) {
        int idx = base + lane;
        int s = 0;
        float coef = 0.f;
        if (idx < end) {
            s = g_edge_src[idx];
            float2 sp = g_spack[s];
            coef = fast_tanh(adst_d + sp.x) * dnd * sp.y;
        }
        stage[w][lane] = make_int2(s, __float_as_int(coef));
        __syncwarp();

        int cnt = end - base;
        if (cnt > 32) cnt = 32;

        int j = 0;
        for (; j + 8 <= cnt; j += 8) {
            int2 p0 = stage[w][j];
            int2 p1 = stage[w][j + 1];
            int2 p2 = stage[w][j + 2];
            int2 p3 = stage[w][j + 3];
            int2 p4 = stage[w][j + 4];
            int2 p5 = stage[w][j + 5];
            int2 p6 = stage[w][j + 6];
            int2 p7 = stage[w][j + 7];
            float2 f0 = *reinterpret_cast<const float2*>(h + (long long)p0.x * D_DIM + lane * 2);
            float2 f1 = *reinterpret_cast<const float2*>(h + (long long)p1.x * D_DIM + lane * 2);
            float2 f2 = *reinterpret_cast<const float2*>(h + (long long)p2.x * D_DIM + lane * 2);
            float2 f3 = *reinterpret_cast<const float2*>(h + (long long)p3.x * D_DIM + lane * 2);
            float2 f4 = *reinterpret_cast<const float2*>(h + (long long)p4.x * D_DIM + lane * 2);
            float2 f5 = *reinterpret_cast<const float2*>(h + (long long)p5.x * D_DIM + lane * 2);
            float2 f6 = *reinterpret_cast<const float2*>(h + (long long)p6.x * D_DIM + lane * 2);
            float2 f7 = *reinterpret_cast<const float2*>(h + (long long)p7.x * D_DIM + lane * 2);
            float c0 = __int_as_float(p0.y);
            float c1 = __int_as_float(p1.y);
            float c2 = __int_as_float(p2.y);
            float c3 = __int_as_float(p3.y);
            float c4 = __int_as_float(p4.y);
            float c5 = __int_as_float(p5.y);
            float c6 = __int_as_float(p6.y);
            float c7 = __int_as_float(p7.y);
            accx = fmaf(c0, f0.x, accx); accy = fmaf(c0, f0.y, accy);
            accx = fmaf(c1, f1.x, accx); accy = fmaf(c1, f1.y, accy);
            accx = fmaf(c2, f2.x, accx); accy = fmaf(c2, f2.y, accy);
            accx = fmaf(c3, f3.x, accx); accy = fmaf(c3, f3.y, accy);
            accx = fmaf(c4, f4.x, accx); accy = fmaf(c4, f4.y, accy);
            accx = fmaf(c5, f5.x, accx); accy = fmaf(c5, f5.y, accy);
            accx = fmaf(c6, f6.x, accx); accy = fmaf(c6, f6.y, accy);
            accx = fmaf(c7, f7.x, accx); accy = fmaf(c7, f7.y, accy);
        }
        for (; j + 4 <= cnt; j += 4) {
            int2 p0 = stage[w][j];
            int2 p1 = stage[w][j + 1];
            int2 p2 = stage[w][j + 2];
            int2 p3 = stage[w][j + 3];
            float2 f0 = *reinterpret_cast<const float2*>(h + (long long)p0.x * D_DIM + lane * 2);
            float2 f1 = *reinterpret_cast<const float2*>(h + (long long)p1.x * D_DIM + lane * 2);
            float2 f2 = *reinterpret_cast<const float2*>(h + (long long)p2.x * D_DIM + lane * 2);
            float2 f3 = *reinterpret_cast<const float2*>(h + (long long)p3.x * D_DIM + lane * 2);
            float c0 = __int_as_float(p0.y);
            float c1 = __int_as_float(p1.y);
            float c2 = __int_as_float(p2.y);
            float c3 = __int_as_float(p3.y);
            accx = fmaf(c0, f0.x, accx); accy = fmaf(c0, f0.y, accy);
            accx = fmaf(c1, f1.x, accx); accy = fmaf(c1, f1.y, accy);
            accx = fmaf(c2, f2.x, accx); accy = fmaf(c2, f2.y, accy);
            accx = fmaf(c3, f3.x, accx); accy = fmaf(c3, f3.y, accy);
        }
        for (; j < cnt; j++) {
            int2 p = stage[w][j];
            float2 fv = *reinterpret_cast<const float2*>(h + (long long)p.x * D_DIM + lane * 2);
            float cj = __int_as_float(p.y);
            accx = fmaf(cj, fv.x, accx);
            accy = fmaf(cj, fv.y, accy);
        }
        __syncwarp();
    }

    *reinterpret_cast<float2*>(out + (long long)d * D_DIM + lane * 2) =
        make_float2(accx, accy);
}

// ---------------------------------------------------------------------------
// Launch (5 kernels)
// ---------------------------------------------------------------------------
extern "C" void kernel_launch(void* const* d_in, const int* in_sizes, int n_in,
                              void* d_out, int out_size)
{
    const float* h      = (const float*)d_in[0];   // (N, 64)
    const float* dnorm  = (const float*)d_in[1];   // (N,)
    const float* gate_w = (const float*)d_in[2];   // (1, 128)
    const float* gate_b = (const float*)d_in[3];   // (1,)
    const int*   src    = (const int*)  d_in[4];   // (E,)
    const int*   dst    = (const int*)  d_in[5];   // (E,)
    float* out = (float*)d_out;                    // (N, 64) float32

    {
        int work = E_EDGES / 4;                    // 400000
        hist_kernel<<<(work + 255) / 256, 256>>>(dst);
    }
    scan_blocks_kernel<<<N_SCAN_BLOCKS, SCAN_BLOCK>>>();
    add_base_kernel<<<N_SCAN_BLOCKS, SCAN_BLOCK>>>();
    {
        int work = E_EDGES / 4;                    // 400000 threads
        scatter_nodes_kernel<<<(work + 255) / 256, 256>>>(
            src, dst, h, dnorm, gate_w, gate_b);
    }
    {
        long long total = (long long)N_NODES * 32;
        int blocks = (int)((total + 255) / 256);
        gather_kernel<<<blocks, 256>>>(h, dnorm, out);
    }
}

// round 17
// speedup vs baseline: 1.0564x; 1.0564x over previous
#include <cuda_runtime.h>
#include <cuda_fp16.h>
#include <cuda_bf16.h>

#define N_NODES 100000
#define D_DIM   64
#define E_EDGES 1600000

#define SCAN_BLOCK 1024
#define N_SCAN_BLOCKS ((N_NODES + SCAN_BLOCK - 1) / SCAN_BLOCK)   // 98

// ---- device scratch (no cudaMalloc allowed; zero-initialized at load) ----
__device__ float  g_adst[N_NODES];          // h[i].w_dst + bias
__device__ float2 g_spack[N_NODES];         // (h[i].w_src, dnorm[i])
__device__ int    g_counts[N_NODES];        // in-degree histogram
                                            // INVARIANT: zero on kernel_launch entry
                                            // (re-zeroed by scan_blocks each call)
__device__ int    g_offsets[N_NODES + 1];   // CSR offsets, BLOCK-LOCAL exclusive
__device__ int    g_blockbase[N_SCAN_BLOCKS];  // per-scan-block global base
__device__ int    g_blocksums[N_SCAN_BLOCKS];
__device__ int    g_scan_done;              // last-block detector (self-resets)
__device__ unsigned short g_rank[E_EDGES];  // edge rank within its dst bucket
__device__ int    g_edge_src[E_EDGES];      // CSR column (src node) list
__device__ __half g_hhalf[N_NODES * D_DIM]; // fp16 mirror of h

__device__ __forceinline__ float fast_tanh(float x) {
    float r;
    asm("tanh.approx.f32 %0, %1;" : "=f"(r) : "f"(x));
    return r;
}

__device__ __forceinline__ int warp_incl_scan(int v, int lane) {
    #pragma unroll
    for (int off = 1; off < 32; off <<= 1) {
        int t = __shfl_up_sync(0xFFFFFFFFu, v, off);
        if (lane >= off) v += t;
    }
    return v;
}

// ---------------------------------------------------------------------------
// K1: histogram + rank. 4 edges/thread; int4 dst read, ushort4 rank store.
// ---------------------------------------------------------------------------
__global__ void hist_kernel(const int* __restrict__ dst)
{
    int t = blockIdx.x * blockDim.x + threadIdx.x;
    if (t >= E_EDGES / 4) return;

    int4 d4 = reinterpret_cast<const int4*>(dst)[t];
    ushort4 r4;
    r4.x = (unsigned short)atomicAdd(&g_counts[d4.x], 1);
    r4.y = (unsigned short)atomicAdd(&g_counts[d4.y], 1);
    r4.z = (unsigned short)atomicAdd(&g_counts[d4.z], 1);
    r4.w = (unsigned short)atomicAdd(&g_counts[d4.w], 1);
    reinterpret_cast<ushort4*>(g_rank)[t] = r4;
}

// ---------------------------------------------------------------------------
// K2: block-local exclusive scan (shuffles) + LAST-BLOCK fixup of the 98
// block bases (no separate add_base kernel). Also re-zeroes counts.
// ---------------------------------------------------------------------------
__global__ void scan_blocks_kernel()
{
    __shared__ int warpsum[32];
    int tid  = threadIdx.x;
    int lane = tid & 31;
    int w    = tid >> 5;
    int b    = blockIdx.x;
    int i    = b * SCAN_BLOCK + tid;

    int v = (i < N_NODES) ? g_counts[i] : 0;
    if (i < N_NODES) g_counts[i] = 0;          // restore hist invariant

    int incl = warp_incl_scan(v, lane);
    if (lane == 31) warpsum[w] = incl;
    __syncthreads();

    if (w == 0) {
        int s = warpsum[lane];
        warpsum[lane] = warp_incl_scan(s, lane) - s;   // exclusive warp bases
    }
    __syncthreads();

    int local_excl = incl - v + warpsum[w];            // block-local exclusive
    if (i < N_NODES) g_offsets[i] = local_excl;
    if (i == N_NODES - 1) g_offsets[N_NODES] = local_excl + v;  // sentinel (block-local)
    if (tid == SCAN_BLOCK - 1) g_blocksums[b] = local_excl + v; // block total

    // last-arriving block computes g_blockbase (exclusive scan of 98 sums)
    __syncthreads();
    __shared__ int s_last;
    if (tid == 0) {
        __threadfence();
        s_last = (atomicAdd(&g_scan_done, 1) == N_SCAN_BLOCKS - 1);
    }
    __syncthreads();
    if (s_last && w == 0) {
        int base = 0;
        #pragma unroll
        for (int c = 0; c < (N_SCAN_BLOCKS + 31) / 32; c++) {
            int idx = c * 32 + lane;
            int bv = (idx < N_SCAN_BLOCKS) ? g_blocksums[idx] : 0;
            int bincl = warp_incl_scan(bv, lane);
            if (idx < N_SCAN_BLOCKS) g_blockbase[idx] = base + bincl - bv;
            base += __shfl_sync(0xFFFFFFFFu, bincl, 31);
        }
        if (lane == 0) g_scan_done = 0;        // self-reset for next replay
    }
}

// ---------------------------------------------------------------------------
// K3: FUSED atomic-free CSR scatter + node dots + fp16 mirror.
// Global offset = g_offsets[d] + g_blockbase[d >> 10] (tiny L1-resident table).
// ---------------------------------------------------------------------------
__global__ void scatter_nodes_kernel(const int*   __restrict__ src,
                                     const int*   __restrict__ dst,
                                     const float* __restrict__ h,
                                     const float* __restrict__ dnorm,
                                     const float* __restrict__ gate_w,
                                     const float* __restrict__ gate_b)
{
    int t = blockIdx.x * blockDim.x + threadIdx.x;

    // ---- scatter part: 4 edges per thread ----
    if (t < E_EDGES / 4) {
        int4    s4 = reinterpret_cast<const int4*>(src)[t];
        int4    d4 = reinterpret_cast<const int4*>(dst)[t];
        ushort4 r4 = reinterpret_cast<const ushort4*>(g_rank)[t];

        int o0 = g_offsets[d4.x] + g_blockbase[d4.x >> 10];
        int o1 = g_offsets[d4.y] + g_blockbase[d4.y >> 10];
        int o2 = g_offsets[d4.z] + g_blockbase[d4.z >> 10];
        int o3 = g_offsets[d4.w] + g_blockbase[d4.w >> 10];

        g_edge_src[o0 + r4.x] = s4.x;
        g_edge_src[o1 + r4.y] = s4.y;
        g_edge_src[o2 + r4.z] = s4.z;
        g_edge_src[o3 + r4.w] = s4.w;
    }

    // ---- node part: warp handles 8 consecutive nodes ----
    int w    = t >> 5;
    int lane = t & 31;
    int nbase = w * 8;
    if (nbase >= N_NODES) return;

    float2 wd = *reinterpret_cast<const float2*>(gate_w + lane * 2);
    float2 ws = *reinterpret_cast<const float2*>(gate_w + D_DIM + lane * 2);
    float bias = gate_b[0];

    #pragma unroll
    for (int k = 0; k < 8; k++) {
        int node = nbase + k;
        if (node >= N_NODES) break;

        float2 hv = *reinterpret_cast<const float2*>(h + (long long)node * D_DIM + lane * 2);

        *reinterpret_cast<__half2*>(g_hhalf + (long long)node * D_DIM + lane * 2) =
            __floats2half2_rn(hv.x, hv.y);

        float pd = hv.x * wd.x + hv.y * wd.y;
        float ps = hv.x * ws.x + hv.y * ws.y;

        #pragma unroll
        for (int off = 16; off > 0; off >>= 1) {
            pd += __shfl_xor_sync(0xFFFFFFFFu, pd, off);
            ps += __shfl_xor_sync(0xFFFFFFFFu, ps, off);
        }

        if (lane == 0) {
            g_adst[node]  = pd + bias;
            g_spack[node] = make_float2(ps, dnorm[node]);
        }
    }
}

// ---------------------------------------------------------------------------
// K4: gather-accumulate (champion form: fp16 rows, smem-staged (s,coef),
// IMAD.WIDE addressing, x8/x4 unroll). beg/end pick up blockbase (uniform).
// ---------------------------------------------------------------------------
__global__ void gather_kernel(const float* __restrict__ dnorm,
                              float* __restrict__ out)
{
    __shared__ int2 stage[8][32];     // 8 warps per 256-thread block

    int tid  = blockIdx.x * blockDim.x + threadIdx.x;
    int d    = tid >> 5;
    int w    = (threadIdx.x >> 5);
    int lane = tid & 31;
    if (d >= N_NODES) return;

    int beg = g_offsets[d]     + g_blockbase[d >> 10];
    int end = g_offsets[d + 1] + g_blockbase[(d + 1) >> 10];

    float adst_d = g_adst[d];
    float dnd    = dnorm[d];

    float accx = 0.f, accy = 0.f;
    const __half* __restrict__ hh = g_hhalf;

    for (int base = beg; base < end; base += 32) {
        int idx = base + lane;
        int s = 0;
        float coef = 0.f;
        if (idx < end) {
            s = g_edge_src[idx];
            float2 sp = g_spack[s];
            coef = fast_tanh(adst_d + sp.x) * dnd * sp.y;
        }
        stage[w][lane] = make_int2(s, __float_as_int(coef));
        __syncwarp();

        int cnt = end - base;
        if (cnt > 32) cnt = 32;

        int j = 0;
        for (; j + 8 <= cnt; j += 8) {
            int2 p0 = stage[w][j];
            int2 p1 = stage[w][j + 1];
            int2 p2 = stage[w][j + 2];
            int2 p3 = stage[w][j + 3];
            int2 p4 = stage[w][j + 4];
            int2 p5 = stage[w][j + 5];
            int2 p6 = stage[w][j + 6];
            int2 p7 = stage[w][j + 7];
            __half2 a0 = *reinterpret_cast<const __half2*>(hh + (long long)p0.x * D_DIM + lane * 2);
            __half2 a1 = *reinterpret_cast<const __half2*>(hh + (long long)p1.x * D_DIM + lane * 2);
            __half2 a2 = *reinterpret_cast<const __half2*>(hh + (long long)p2.x * D_DIM + lane * 2);
            __half2 a3 = *reinterpret_cast<const __half2*>(hh + (long long)p3.x * D_DIM + lane * 2);
            __half2 a4 = *reinterpret_cast<const __half2*>(hh + (long long)p4.x * D_DIM + lane * 2);
            __half2 a5 = *reinterpret_cast<const __half2*>(hh + (long long)p5.x * D_DIM + lane * 2);
            __half2 a6 = *reinterpret_cast<const __half2*>(hh + (long long)p6.x * D_DIM + lane * 2);
            __half2 a7 = *reinterpret_cast<const __half2*>(hh + (long long)p7.x * D_DIM + lane * 2);
            float2 f0 = __half22float2(a0);
            float2 f1 = __half22float2(a1);
            float2 f2 = __half22float2(a2);
            float2 f3 = __half22float2(a3);
            float2 f4 = __half22float2(a4);
            float2 f5 = __half22float2(a5);
            float2 f6 = __half22float2(a6);
            float2 f7 = __half22float2(a7);
            float c0 = __int_as_float(p0.y);
            float c1 = __int_as_float(p1.y);
            float c2 = __int_as_float(p2.y);
            float c3 = __int_as_float(p3.y);
            float c4 = __int_as_float(p4.y);
            float c5 = __int_as_float(p5.y);
            float c6 = __int_as_float(p6.y);
            float c7 = __int_as_float(p7.y);
            accx = fmaf(c0, f0.x, accx); accy = fmaf(c0, f0.y, accy);
            accx = fmaf(c1, f1.x, accx); accy = fmaf(c1, f1.y, accy);
            accx = fmaf(c2, f2.x, accx); accy = fmaf(c2, f2.y, accy);
            accx = fmaf(c3, f3.x, accx); accy = fmaf(c3, f3.y, accy);
            accx = fmaf(c4, f4.x, accx); accy = fmaf(c4, f4.y, accy);
            accx = fmaf(c5, f5.x, accx); accy = fmaf(c5, f5.y, accy);
            accx = fmaf(c6, f6.x, accx); accy = fmaf(c6, f6.y, accy);
            accx = fmaf(c7, f7.x, accx); accy = fmaf(c7, f7.y, accy);
        }
        for (; j + 4 <= cnt; j += 4) {
            int2 p0 = stage[w][j];
            int2 p1 = stage[w][j + 1];
            int2 p2 = stage[w][j + 2];
            int2 p3 = stage[w][j + 3];
            __half2 a0 = *reinterpret_cast<const __half2*>(hh + (long long)p0.x * D_DIM + lane * 2);
            __half2 a1 = *reinterpret_cast<const __half2*>(hh + (long long)p1.x * D_DIM + lane * 2);
            __half2 a2 = *reinterpret_cast<const __half2*>(hh + (long long)p2.x * D_DIM + lane * 2);
            __half2 a3 = *reinterpret_cast<const __half2*>(hh + (long long)p3.x * D_DIM + lane * 2);
            float2 f0 = __half22float2(a0);
            float2 f1 = __half22float2(a1);
            float2 f2 = __half22float2(a2);
            float2 f3 = __half22float2(a3);
            float c0 = __int_as_float(p0.y);
            float c1 = __int_as_float(p1.y);
            float c2 = __int_as_float(p2.y);
            float c3 = __int_as_float(p3.y);
            accx = fmaf(c0, f0.x, accx); accy = fmaf(c0, f0.y, accy);
            accx = fmaf(c1, f1.x, accx); accy = fmaf(c1, f1.y, accy);
            accx = fmaf(c2, f2.x, accx); accy = fmaf(c2, f2.y, accy);
            accx = fmaf(c3, f3.x, accx); accy = fmaf(c3, f3.y, accy);
        }
        for (; j < cnt; j++) {
            int2 p = stage[w][j];
            __half2 av = *reinterpret_cast<const __half2*>(hh + (long long)p.x * D_DIM + lane * 2);
            float2 fv = __half22float2(av);
            float cj = __int_as_float(p.y);
            accx = fmaf(cj, fv.x, accx);
            accy = fmaf(cj, fv.y, accy);
        }
        __syncwarp();
    }

    *reinterpret_cast<float2*>(out + (long long)d * D_DIM + lane * 2) =
        make_float2(accx, accy);
}

// ---------------------------------------------------------------------------
// Launch (4 kernels)
// ---------------------------------------------------------------------------
extern "C" void kernel_launch(void* const* d_in, const int* in_sizes, int n_in,
                              void* d_out, int out_size)
{
    const float* h      = (const float*)d_in[0];   // (N, 64)
    const float* dnorm  = (const float*)d_in[1];   // (N,)
    const float* gate_w = (const float*)d_in[2];   // (1, 128)
    const float* gate_b = (const float*)d_in[3];   // (1,)
    const int*   src    = (const int*)  d_in[4];   // (E,)
    const int*   dst    = (const int*)  d_in[5];   // (E,)
    float* out = (float*)d_out;                    // (N, 64) float32

    {
        int work = E_EDGES / 4;                    // 400000
        hist_kernel<<<(work + 255) / 256, 256>>>(dst);
    }
    scan_blocks_kernel<<<N_SCAN_BLOCKS, SCAN_BLOCK>>>();
    {
        int work = E_EDGES / 4;                    // 400000 threads
        scatter_nodes_kernel<<<(work + 255) / 256, 256>>>(
            src, dst, h, dnorm, gate_w, gate_b);
    }
    {
        long long total = (long long)N_NODES * 32;
        int blocks = (int)((total + 255) / 256);
        gather_kernel<<<blocks, 256>>>(dnorm, out);
    }
}